// round 13
// baseline (speedup 1.0000x reference)
#include <cuda_runtime.h>
#include <math.h>

// Problem constants
constexpr int NN = 325;           // nodes
constexpr int BBATCH = 64;        // batch
constexpr int DD = 64;            // hidden units
constexpr int PP = 12;            // encoder steps
constexpr int QQ = 12;            // decoder steps
constexpr int TT = 24;            // total steps
constexpr int MROW = NN * BBATCH; // 20800 rows, layout row = n*B + b

// ---------------- device scratch (static, no allocation) ----------------
__device__ float g_vals[2 * NN * NN];
__device__ int   g_cols[2 * NN * NN];
__device__ int   g_cnt[2 * NN];
__device__ float g_te[BBATCH * TT * DD];                 // te embeddings (b,t,d)
__device__ float g_XE[(size_t)TT * MROW * DD];           // x inputs per step
__device__ float g_SX[(size_t)TT * MROW * 2 * DD];       // [S0x | S1x]
__device__ float g_Gx[(size_t)TT * MROW * 2 * DD];       // x-contribution to gate preact (+bg)
__device__ float g_Cx[(size_t)TT * MROW * DD];           // x-contribution to cand preact (+bc)
__device__ float g_SV[(size_t)MROW * 2 * DD];            // per-step [S0v | S1v]
__device__ float g_h [(size_t)MROW * DD];
__device__ float g_rh[(size_t)MROW * DD];
__device__ float g_RU[(size_t)MROW * 2 * DD];            // [r | u] after sigmoid

// ---------------- CSR build (deterministic ballot compaction) -----------
__global__ void build_csr_kernel(const float* __restrict__ S0,
                                 const float* __restrict__ S1) {
    int m = blockIdx.x, sup = blockIdx.y;
    const float* S = sup ? S1 : S0;
    int lane = threadIdx.x;            // blockDim = 32
    int base = (sup * NN + m) * NN;
    int cnt = 0;
    for (int start = 0; start < NN; start += 32) {
        int n = start + lane;
        float v = (n < NN) ? S[m * NN + n] : 0.f;
        unsigned mask = __ballot_sync(0xffffffffu, v != 0.f);
        if (v != 0.f) {
            int pos = cnt + __popc(mask & ((1u << lane) - 1u));
            g_cols[base + pos] = n;
            g_vals[base + pos] = v;
        }
        cnt += __popc(mask);
    }
    if (lane == 0) g_cnt[sup * NN + m] = cnt;
}

// ---------------- temporal embedding -------------------------------------
__global__ void te_kernel(const int* __restrict__ TE,
                          const float* __restrict__ W1, const float* __restrict__ b1,
                          const float* __restrict__ W2, const float* __restrict__ b2) {
    int bt = blockIdx.x;     // b*24 + t
    int d = threadIdx.x;     // 64 threads
    __shared__ float sh[DD];
    int wd = TE[bt * 2 + 0];
    int td = TE[bt * 2 + 1];
    float v = W1[wd * DD + d] + W1[(7 + td) * DD + d] + b1[d];
    sh[d] = fmaxf(v, 0.f);
    __syncthreads();
    float acc = b2[d];
#pragma unroll
    for (int k = 0; k < DD; k++) acc += sh[k] * W2[k * DD + d];
    g_te[bt * DD + d] = acc;
}

// ---------------- XE build: embX + te + E_se (enc), te + E_se (dec) ------
__global__ void xe_kernel(const float* __restrict__ X,
                          const float* __restrict__ Win1, const float* __restrict__ bin1,
                          const float* __restrict__ Win2, const float* __restrict__ bin2,
                          const float* __restrict__ Ese) {
    long rowg = (long)blockIdx.x * 2 + (threadIdx.x >> 6);  // 2 rows per block
    int d  = threadIdx.x & 63;
    int lr = threadIdx.x >> 6;
    int t = (int)(rowg / MROW);
    int r = (int)(rowg % MROW);
    int n = r / BBATCH, b = r % BBATCH;
    __shared__ float sh[2][DD];
    float out = 0.f;
    if (t < PP) {  // uniform per block (MROW even)
        float x = X[(size_t)(b * PP + t) * NN + n];
        sh[lr][d] = fmaxf(x * Win1[d] + bin1[d], 0.f);
        __syncthreads();
        float acc = bin2[d];
#pragma unroll
        for (int k = 0; k < DD; k++) acc += sh[lr][k] * Win2[k * DD + d];
        out = acc;
    }
    out += g_te[(b * TT + t) * DD + d] + Ese[n * DD + d];
    g_XE[rowg * DD + d] = out;
}

// ---------------- SpMM: out[m,b,sup*64+c] = sum_n S[m,n]*V[n,b,c] --------
// src: 0 = XE->SX (grid.y = 24), 1 = h->SV, 2 = rh->SV
__global__ __launch_bounds__(256) void spmm_kernel(int src) {
    int m = blockIdx.x;
    int t = blockIdx.y;
    int sup = blockIdx.z;
    const float* V;
    float* O;
    if (src == 0)      { V = g_XE + (size_t)t * MROW * DD; O = g_SX + (size_t)t * MROW * (2 * DD); }
    else if (src == 1) { V = g_h;  O = g_SV; }
    else               { V = g_rh; O = g_SV; }

    __shared__ float sval[NN];
    __shared__ int   scol[NN];
    int cnt  = g_cnt[sup * NN + m];
    int base = (sup * NN + m) * NN;
    for (int j = threadIdx.x; j < cnt; j += 256) {
        sval[j] = g_vals[base + j];
        scol[j] = g_cols[base + j];
    }
    __syncthreads();

    int c4 = threadIdx.x & 15;   // 16 float4 groups = 64 floats
    int bq = threadIdx.x >> 4;   // 16
    float4 acc[4];
#pragma unroll
    for (int q = 0; q < 4; q++) acc[q] = make_float4(0.f, 0.f, 0.f, 0.f);

    for (int j = 0; j < cnt; j++) {
        int n = scol[j];
        float v = sval[j];
        const float* vrow = V + (size_t)n * BBATCH * DD + c4 * 4;
#pragma unroll
        for (int q = 0; q < 4; q++) {
            int b = bq + q * 16;
            float4 x = *reinterpret_cast<const float4*>(vrow + (size_t)b * DD);
            acc[q].x = fmaf(v, x.x, acc[q].x);
            acc[q].y = fmaf(v, x.y, acc[q].y);
            acc[q].z = fmaf(v, x.z, acc[q].z);
            acc[q].w = fmaf(v, x.w, acc[q].w);
        }
    }
#pragma unroll
    for (int q = 0; q < 4; q++) {
        int b = bq + q * 16;
        *reinterpret_cast<float4*>(O + ((size_t)(m * BBATCH + b)) * (2 * DD) + sup * DD + c4 * 4) = acc[q];
    }
}

// ---------------- fused GEMM (4 modes) ------------------------------------
// A = [A0(64) | A1(128)], K=192; W row map: x-part rows {0:64,128:192,256:320},
// h-part rows {64:128,192:256,320:384}.
// MODE 0: precompute Gx = A@Wg_x + bg            (A0=XE[t], A1=SX[t], grid.y=t)
// MODE 1: precompute Cx = A@Wc_x + bc
// MODE 2: RU = sigmoid(A@Wg_h + Gx[t]); rh = r*h (A0=h, A1=SV)
// MODE 3: c = tanh(A@Wc_h + Cx[t]); h = u*h+(1-u)*c (A0=rh, A1=SV)
template<int BN, int MODE>
__global__ __launch_bounds__(256)
void gemm_kernel(const float* __restrict__ Wenc, const float* __restrict__ Wdec,
                 const float* __restrict__ benc, const float* __restrict__ bdec,
                 int tstep) {
    constexpr int BM = 64, BK = 32, KTOT = 192;
    constexpr int TM = 4, TN = BN / 16;
    int t = (MODE < 2) ? blockIdx.y : tstep;
    const float* W = (t < PP) ? Wenc : Wdec;

    const float* A0;
    const float* A1;
    if (MODE == 0 || MODE == 1) {
        A0 = g_XE + (size_t)t * MROW * DD;
        A1 = g_SX + (size_t)t * MROW * (2 * DD);
    } else if (MODE == 2) { A0 = g_h;  A1 = g_SV; }
    else                  { A0 = g_rh; A1 = g_SV; }

    int mbase = blockIdx.x * BM;
    __shared__ float As[BM][BK + 1];
    __shared__ __align__(16) float Ws[BK][BN];

    int tid = threadIdx.x;
    int tx = tid & 15, ty = tid >> 4;
    float acc[TM][TN] = {};

    for (int ki = 0; ki < KTOT; ki += BK) {
#pragma unroll
        for (int i = 0; i < (BM * BK) / 256; i++) {
            int e = tid + i * 256;
            int mm = e >> 5, kk = e & 31;
            int k = ki + kk;
            size_t row = (size_t)(mbase + mm);
            As[mm][kk] = (k < DD) ? A0[row * DD + k]
                                  : A1[row * (size_t)(2 * DD) + (k - DD)];
        }
#pragma unroll
        for (int i = 0; i < (BK * BN) / 256; i++) {
            int e = tid + i * 256;
            int nn = e % BN, kk = e / BN;
            int k = ki + kk;
            int wrow = ((MODE == 0 || MODE == 1) ? 0 : DD) + k + ((k >> 6) << 6);
            Ws[kk][nn] = W[wrow * BN + nn];
        }
        __syncthreads();
#pragma unroll
        for (int kk = 0; kk < BK; kk++) {
            float a[TM], bb[TN];
#pragma unroll
            for (int i = 0; i < TM; i++) a[i] = As[ty * TM + i][kk];
            const float4* wv = reinterpret_cast<const float4*>(&Ws[kk][tx * TN]);
#pragma unroll
            for (int j = 0; j < TN / 4; j++) {
                float4 w = wv[j];
                bb[4 * j + 0] = w.x; bb[4 * j + 1] = w.y;
                bb[4 * j + 2] = w.z; bb[4 * j + 3] = w.w;
            }
#pragma unroll
            for (int i = 0; i < TM; i++)
#pragma unroll
                for (int j = 0; j < TN; j++)
                    acc[i][j] = fmaf(a[i], bb[j], acc[i][j]);
        }
        __syncthreads();
    }

    const float* bias = (t < PP) ? benc : bdec;
#pragma unroll
    for (int i = 0; i < TM; i++) {
        size_t row = (size_t)(mbase + ty * TM + i);
#pragma unroll
        for (int j = 0; j < TN; j++) {
            int col = tx * TN + j;
            float v = acc[i][j];
            if (MODE == 0) {
                g_Gx[((size_t)t * MROW + row) * 128 + col] = v + bias[col];
            } else if (MODE == 1) {
                g_Cx[((size_t)t * MROW + row) * 64 + col] = v + bias[col];
            } else if (MODE == 2) {
                v += g_Gx[((size_t)t * MROW + row) * 128 + col];
                float s = 1.f / (1.f + expf(-v));
                g_RU[row * 128 + col] = s;
                if (col < DD) g_rh[row * DD + col] = s * g_h[row * DD + col];
            } else {
                v += g_Cx[((size_t)t * MROW + row) * 64 + col];
                float c = tanhf(v);
                float u = g_RU[row * 128 + DD + col];
                float hold = g_h[row * DD + col];
                g_h[row * DD + col] = u * hold + (1.f - u) * c;
            }
        }
    }
}

// ---------------- output head: relu(h@W1+b1)@W2+b2 -> out[b,tq,n] --------
__global__ void outhead_kernel(const float* __restrict__ W1, const float* __restrict__ b1,
                               const float* __restrict__ W2, const float* __restrict__ b2,
                               float* __restrict__ out, int tq) {
    int lr = threadIdx.x >> 6;        // 2 rows/block
    int d  = threadIdx.x & 63;
    int row = blockIdx.x * 2 + lr;    // n*B + b
    __shared__ float shH[2][DD];
    __shared__ float red[2][2];
    shH[lr][d] = g_h[(size_t)row * DD + d];
    __syncthreads();
    float acc = b1[d];
#pragma unroll
    for (int k = 0; k < DD; k++) acc += shH[lr][k] * W1[k * DD + d];
    acc = fmaxf(acc, 0.f) * W2[d];
#pragma unroll
    for (int off = 16; off; off >>= 1) acc += __shfl_down_sync(0xffffffffu, acc, off);
    if ((d & 31) == 0) red[lr][d >> 5] = acc;
    __syncthreads();
    if (d == 0) {
        float v = red[lr][0] + red[lr][1] + b2[0];
        int n = row / BBATCH, b = row % BBATCH;
        out[(size_t)(b * QQ + tq) * NN + n] = v;
    }
}

__global__ void zero_h_kernel() {
    size_t i = (size_t)blockIdx.x * 256 + threadIdx.x;
    if (i < (size_t)MROW * DD) g_h[i] = 0.f;
}

// ---------------- launcher -------------------------------------------------
extern "C" void kernel_launch(void* const* d_in, const int* in_sizes, int n_in,
                              void* d_out, int out_size) {
    (void)in_sizes; (void)n_in; (void)out_size;
    const float* X      = (const float*)d_in[0];
    const int*   TE     = (const int*)  d_in[1];
    const float* S0     = (const float*)d_in[2];
    const float* S1     = (const float*)d_in[3];
    const float* W_te1  = (const float*)d_in[4];
    const float* b_te1  = (const float*)d_in[5];
    const float* W_te2  = (const float*)d_in[6];
    const float* b_te2  = (const float*)d_in[7];
    const float* E_se   = (const float*)d_in[8];
    const float* W_in1  = (const float*)d_in[9];
    const float* b_in1  = (const float*)d_in[10];
    const float* W_in2  = (const float*)d_in[11];
    const float* b_in2  = (const float*)d_in[12];
    const float* enc_Wg = (const float*)d_in[13];
    const float* enc_bg = (const float*)d_in[14];
    const float* enc_Wc = (const float*)d_in[15];
    const float* enc_bc = (const float*)d_in[16];
    const float* dec_Wg = (const float*)d_in[17];
    const float* dec_bg = (const float*)d_in[18];
    const float* dec_Wc = (const float*)d_in[19];
    const float* dec_bc = (const float*)d_in[20];
    const float* W_out1 = (const float*)d_in[21];
    const float* b_out1 = (const float*)d_in[22];
    const float* W_out2 = (const float*)d_in[23];
    const float* b_out2 = (const float*)d_in[24];
    float* out = (float*)d_out;

    // prologue
    build_csr_kernel<<<dim3(NN, 2), 32>>>(S0, S1);
    te_kernel<<<BBATCH * TT, DD>>>(TE, W_te1, b_te1, W_te2, b_te2);
    xe_kernel<<<(TT * MROW) / 2, 128>>>(X, W_in1, b_in1, W_in2, b_in2, E_se);
    spmm_kernel<<<dim3(NN, TT, 2), 256>>>(0);                                  // SX
    gemm_kernel<128, 0><<<dim3(MROW / 64, TT), 256>>>(enc_Wg, dec_Wg, enc_bg, dec_bg, 0); // Gx
    gemm_kernel<64, 1><<<dim3(MROW / 64, TT), 256>>>(enc_Wc, dec_Wc, enc_bc, dec_bc, 0);  // Cx
    zero_h_kernel<<<(MROW * DD) / 256, 256>>>();

    // recurrence: 12 encoder + 12 decoder steps
    for (int t = 0; t < TT; t++) {
        spmm_kernel<<<dim3(NN, 1, 2), 256>>>(1);                               // [S0h|S1h]
        gemm_kernel<128, 2><<<dim3(MROW / 64, 1), 256>>>(enc_Wg, dec_Wg, nullptr, nullptr, t); // RU + rh
        spmm_kernel<<<dim3(NN, 1, 2), 256>>>(2);                               // [S0rh|S1rh]
        gemm_kernel<64, 3><<<dim3(MROW / 64, 1), 256>>>(enc_Wc, dec_Wc, nullptr, nullptr, t);  // c, h-update
        if (t >= PP)
            outhead_kernel<<<MROW / 2, 128>>>(W_out1, b_out1, W_out2, b_out2, out, t - PP);
    }
}

// round 15
// speedup vs baseline: 1.1957x; 1.1957x over previous
#include <cuda_runtime.h>
#include <cstdint>
#include <math.h>

// Problem constants
constexpr int NN = 325;           // nodes
constexpr int BBATCH = 64;        // batch
constexpr int DD = 64;            // hidden units
constexpr int PP = 12;            // encoder steps
constexpr int QQ = 12;            // decoder steps
constexpr int TT = 24;            // total steps
constexpr int MROW = NN * BBATCH; // 20800 rows, layout row = n*B + b
constexpr int MTILES = (MROW + 127) / 128; // 163

// ---------------- device scratch (static, no allocation) ----------------
__device__ float g_vals[2 * NN * NN];
__device__ int   g_cols[2 * NN * NN];
__device__ int   g_cnt[2 * NN];
__device__ float g_te[BBATCH * TT * DD];                 // te embeddings (b,t,d)
__device__ float g_XE[(size_t)TT * MROW * DD];           // x inputs per step
__device__ float g_SX[(size_t)TT * MROW * 2 * DD];       // [S0x | S1x]
__device__ float g_Gx[(size_t)TT * MROW * 2 * DD];       // x-contribution to gate preact (+bg)
__device__ float g_Cx[(size_t)TT * MROW * DD];           // x-contribution to cand preact (+bc)
__device__ float g_SV[(size_t)MROW * 2 * DD];            // per-step [S0v | S1v]
__device__ float g_h [(size_t)MROW * DD];
__device__ float g_rh[(size_t)MROW * DD];
__device__ float g_RU[(size_t)MROW * 2 * DD];            // [r | u] after sigmoid

// ---------------- helpers -------------------------------------------------
__device__ __forceinline__ uint32_t to_tf32(float x) {
    uint32_t u;
    asm("cvt.rna.tf32.f32 %0, %1;" : "=r"(u) : "f"(x));
    return u;
}

__device__ __forceinline__ void mma_tf32(float c[4], const uint32_t a[4], const uint32_t b[2]) {
    asm volatile(
        "mma.sync.aligned.m16n8k8.row.col.f32.tf32.tf32.f32 "
        "{%0,%1,%2,%3}, {%4,%5,%6,%7}, {%8,%9}, {%0,%1,%2,%3};"
        : "+f"(c[0]), "+f"(c[1]), "+f"(c[2]), "+f"(c[3])
        : "r"(a[0]), "r"(a[1]), "r"(a[2]), "r"(a[3]), "r"(b[0]), "r"(b[1]));
}

// ---------------- CSR build (deterministic ballot compaction) -----------
__global__ void build_csr_kernel(const float* __restrict__ S0,
                                 const float* __restrict__ S1) {
    int m = blockIdx.x, sup = blockIdx.y;
    const float* S = sup ? S1 : S0;
    int lane = threadIdx.x;            // blockDim = 32
    int base = (sup * NN + m) * NN;
    int cnt = 0;
    for (int start = 0; start < NN; start += 32) {
        int n = start + lane;
        float v = (n < NN) ? S[m * NN + n] : 0.f;
        unsigned mask = __ballot_sync(0xffffffffu, v != 0.f);
        if (v != 0.f) {
            int pos = cnt + __popc(mask & ((1u << lane) - 1u));
            g_cols[base + pos] = n;
            g_vals[base + pos] = v;
        }
        cnt += __popc(mask);
    }
    if (lane == 0) g_cnt[sup * NN + m] = cnt;
}

// ---------------- temporal embedding -------------------------------------
__global__ void te_kernel(const int* __restrict__ TE,
                          const float* __restrict__ W1, const float* __restrict__ b1,
                          const float* __restrict__ W2, const float* __restrict__ b2) {
    int bt = blockIdx.x;     // b*24 + t
    int d = threadIdx.x;     // 64 threads
    __shared__ float sh[DD];
    int wd = TE[bt * 2 + 0];
    int td = TE[bt * 2 + 1];
    float v = W1[wd * DD + d] + W1[(7 + td) * DD + d] + b1[d];
    sh[d] = fmaxf(v, 0.f);
    __syncthreads();
    float acc = b2[d];
#pragma unroll
    for (int k = 0; k < DD; k++) acc += sh[k] * W2[k * DD + d];
    g_te[bt * DD + d] = acc;
}

// ---------------- XE build: embX + te + E_se (enc), te + E_se (dec) ------
__global__ void xe_kernel(const float* __restrict__ X,
                          const float* __restrict__ Win1, const float* __restrict__ bin1,
                          const float* __restrict__ Win2, const float* __restrict__ bin2,
                          const float* __restrict__ Ese) {
    long rowg = (long)blockIdx.x * 2 + (threadIdx.x >> 6);  // 2 rows per block
    int d  = threadIdx.x & 63;
    int lr = threadIdx.x >> 6;
    int t = (int)(rowg / MROW);
    int r = (int)(rowg % MROW);
    int n = r / BBATCH, b = r % BBATCH;
    __shared__ float sh[2][DD];
    float out = 0.f;
    if (t < PP) {  // uniform per block (MROW even)
        float x = X[(size_t)(b * PP + t) * NN + n];
        sh[lr][d] = fmaxf(x * Win1[d] + bin1[d], 0.f);
        __syncthreads();
        float acc = bin2[d];
#pragma unroll
        for (int k = 0; k < DD; k++) acc += sh[lr][k] * Win2[k * DD + d];
        out = acc;
    }
    out += g_te[(b * TT + t) * DD + d] + Ese[n * DD + d];
    g_XE[rowg * DD + d] = out;
}

// ---------------- SpMM: out[m,b,sup*64+c] = sum_n S[m,n]*V[n,b,c] --------
// src: 0 = XE->SX (grid.y = 24), 1 = h->SV, 2 = rh->SV
__global__ __launch_bounds__(256) void spmm_kernel(int src) {
    int m = blockIdx.x;
    int t = blockIdx.y;
    int sup = blockIdx.z;
    const float* V;
    float* O;
    if (src == 0)      { V = g_XE + (size_t)t * MROW * DD; O = g_SX + (size_t)t * MROW * (2 * DD); }
    else if (src == 1) { V = g_h;  O = g_SV; }
    else               { V = g_rh; O = g_SV; }

    __shared__ float sval[NN];
    __shared__ int   scol[NN];
    int cnt  = g_cnt[sup * NN + m];
    int base = (sup * NN + m) * NN;
    for (int j = threadIdx.x; j < cnt; j += 256) {
        sval[j] = g_vals[base + j];
        scol[j] = g_cols[base + j];
    }
    __syncthreads();

    int c4 = threadIdx.x & 15;   // 16 float4 groups = 64 floats
    int bq = threadIdx.x >> 4;   // 16
    float4 acc[4];
#pragma unroll
    for (int q = 0; q < 4; q++) acc[q] = make_float4(0.f, 0.f, 0.f, 0.f);

    for (int j = 0; j < cnt; j++) {
        int n = scol[j];
        float v = sval[j];
        const float* vrow = V + (size_t)n * BBATCH * DD + c4 * 4;
#pragma unroll
        for (int q = 0; q < 4; q++) {
            int b = bq + q * 16;
            float4 x = *reinterpret_cast<const float4*>(vrow + (size_t)b * DD);
            acc[q].x = fmaf(v, x.x, acc[q].x);
            acc[q].y = fmaf(v, x.y, acc[q].y);
            acc[q].z = fmaf(v, x.z, acc[q].z);
            acc[q].w = fmaf(v, x.w, acc[q].w);
        }
    }
#pragma unroll
    for (int q = 0; q < 4; q++) {
        int b = bq + q * 16;
        *reinterpret_cast<float4*>(O + ((size_t)(m * BBATCH + b)) * (2 * DD) + sup * DD + c4 * 4) = acc[q];
    }
}

// ---------------- tf32 tensor-core GEMM (4 modes) --------------------------
// A = [A0(64) | A1(128)], K=192; W row map: x-part rows {0:64,128:192,256:320},
// h-part rows {64:128,192:256,320:384}.
// MODE 0: Gx = A@Wg_x + bg   (A0=XE[t], A1=SX[t], grid.y = t), BN=128
// MODE 1: Cx = A@Wc_x + bc   BN=64
// MODE 2: RU = sigmoid(A@Wg_h + Gx[t]); rh = r*h  (A0=h, A1=SV), BN=128
// MODE 3: c = tanh(A@Wc_h + Cx[t]); h = u*h+(1-u)*c (A0=rh, A1=SV), BN=64
//
// Block: 256 threads = 8 warps in 4(m) x 2(n); block tile 128 x BN, BK=32.
// Smem fragment layout uses row stride 36 words: fragment LDS bank index is
// (4*(lane>>2) + (lane&3)) mod 32 -> a perfect permutation, conflict-free.
template<int BN, int MODE>
__global__ __launch_bounds__(256, 2)
void mma_gemm_kernel(const float* __restrict__ Wenc, const float* __restrict__ Wdec,
                     const float* __restrict__ benc, const float* __restrict__ bdec,
                     int tstep) {
    constexpr int BM = 128, BK = 32, KTOT = 192;
    constexpr int NJ = (BN / 2) / 8;          // n8 tiles per warp (8 or 4)
    int t = (MODE < 2) ? blockIdx.y : tstep;
    const float* W = (t < PP) ? Wenc : Wdec;

    const float* A0;
    const float* A1;
    if (MODE == 0 || MODE == 1) {
        A0 = g_XE + (size_t)t * MROW * DD;
        A1 = g_SX + (size_t)t * MROW * (2 * DD);
    } else if (MODE == 2) { A0 = g_h;  A1 = g_SV; }
    else                  { A0 = g_rh; A1 = g_SV; }

    int mbase = blockIdx.x * BM;

    __shared__ uint32_t As[BM][36];   // [m][k], tf32 bits, stride 36
    __shared__ uint32_t Ws[BN][36];   // [n][k], tf32 bits, stride 36

    int tid  = threadIdx.x;
    int lane = tid & 31;
    int wid  = tid >> 5;
    int wm = (wid >> 1) * 32;         // warp row offset (0,32,64,96)
    int wn = (wid & 1) * (BN / 2);    // warp col offset

    float acc[2][NJ][4];
#pragma unroll
    for (int mi = 0; mi < 2; mi++)
#pragma unroll
        for (int nj = 0; nj < NJ; nj++)
#pragma unroll
            for (int e = 0; e < 4; e++) acc[mi][nj][e] = 0.f;

    for (int ki = 0; ki < KTOT; ki += BK) {
        // --- load A tile: 128x32, coalesced on k; conflict-free STS ---
#pragma unroll
        for (int i = 0; i < (BM * BK) / 256; i++) {
            int e  = tid + i * 256;
            int mm = e >> 5, kk = e & 31;
            int k  = ki + kk;
            int row = mbase + mm;
            float v = 0.f;
            if (row < MROW)
                v = (k < DD) ? A0[(size_t)row * DD + k]
                             : A1[(size_t)row * (2 * DD) + (k - DD)];
            As[mm][kk] = to_tf32(v);
        }
        // --- load W tile (transposed into [n][k]) ---
#pragma unroll
        for (int i = 0; i < (BK * BN) / 256; i++) {
            int e  = tid + i * 256;
            int nn = e % BN, kk = e / BN;
            int k  = ki + kk;
            int wrow = ((MODE == 0 || MODE == 1) ? 0 : DD) + k + ((k >> 6) << 6);
            Ws[nn][kk] = to_tf32(W[wrow * BN + nn]);
        }
        __syncthreads();

#pragma unroll
        for (int k8 = 0; k8 < BK; k8 += 8) {
            uint32_t a[2][4];
            int ar = wm + (lane >> 2);
            int ak = k8 + (lane & 3);
#pragma unroll
            for (int mi = 0; mi < 2; mi++) {
                int r = ar + mi * 16;
                a[mi][0] = As[r][ak];
                a[mi][1] = As[r + 8][ak];
                a[mi][2] = As[r][ak + 4];
                a[mi][3] = As[r + 8][ak + 4];
            }
            uint32_t b[NJ][2];
#pragma unroll
            for (int nj = 0; nj < NJ; nj++) {
                int bn = wn + nj * 8 + (lane >> 2);
                int bk = k8 + (lane & 3);
                b[nj][0] = Ws[bn][bk];
                b[nj][1] = Ws[bn][bk + 4];
            }
#pragma unroll
            for (int mi = 0; mi < 2; mi++)
#pragma unroll
                for (int nj = 0; nj < NJ; nj++)
                    mma_tf32(acc[mi][nj], a[mi], b[nj]);
        }
        __syncthreads();
    }

    // --- epilogue ---
    const float* bias = (t < PP) ? benc : bdec;
#pragma unroll
    for (int mi = 0; mi < 2; mi++) {
        int r0 = mbase + wm + mi * 16 + (lane >> 2);
#pragma unroll
        for (int nj = 0; nj < NJ; nj++) {
            int col0 = wn + nj * 8 + 2 * (lane & 3);
#pragma unroll
            for (int e = 0; e < 4; e++) {
                int row = r0 + (e >> 1) * 8;
                int col = col0 + (e & 1);
                if (row >= MROW) continue;
                float v = acc[mi][nj][e];
                if (MODE == 0) {
                    g_Gx[((size_t)t * MROW + row) * 128 + col] = v + bias[col];
                } else if (MODE == 1) {
                    g_Cx[((size_t)t * MROW + row) * 64 + col] = v + bias[col];
                } else if (MODE == 2) {
                    v += g_Gx[((size_t)t * MROW + row) * 128 + col];
                    float s = 1.f / (1.f + expf(-v));
                    g_RU[(size_t)row * 128 + col] = s;
                    if (col < DD) g_rh[(size_t)row * DD + col] = s * g_h[(size_t)row * DD + col];
                } else {
                    v += g_Cx[((size_t)t * MROW + row) * 64 + col];
                    float c = tanhf(v);
                    float u = g_RU[(size_t)row * 128 + DD + col];
                    float hold = g_h[(size_t)row * DD + col];
                    g_h[(size_t)row * DD + col] = u * hold + (1.f - u) * c;
                }
            }
        }
    }
}

// ---------------- output head: relu(h@W1+b1)@W2+b2 -> out[b,tq,n] --------
__global__ void outhead_kernel(const float* __restrict__ W1, const float* __restrict__ b1,
                               const float* __restrict__ W2, const float* __restrict__ b2,
                               float* __restrict__ out, int tq) {
    int lr = threadIdx.x >> 6;        // 2 rows/block
    int d  = threadIdx.x & 63;
    int row = blockIdx.x * 2 + lr;    // n*B + b
    __shared__ float shH[2][DD];
    __shared__ float red[2][2];
    shH[lr][d] = g_h[(size_t)row * DD + d];
    __syncthreads();
    float acc = b1[d];
#pragma unroll
    for (int k = 0; k < DD; k++) acc += shH[lr][k] * W1[k * DD + d];
    acc = fmaxf(acc, 0.f) * W2[d];
#pragma unroll
    for (int off = 16; off; off >>= 1) acc += __shfl_down_sync(0xffffffffu, acc, off);
    if ((d & 31) == 0) red[lr][d >> 5] = acc;
    __syncthreads();
    if (d == 0) {
        float v = red[lr][0] + red[lr][1] + b2[0];
        int n = row / BBATCH, b = row % BBATCH;
        out[(size_t)(b * QQ + tq) * NN + n] = v;
    }
}

__global__ void zero_h_kernel() {
    size_t i = (size_t)blockIdx.x * 256 + threadIdx.x;
    if (i < (size_t)MROW * DD) g_h[i] = 0.f;
}

// ---------------- launcher -------------------------------------------------
extern "C" void kernel_launch(void* const* d_in, const int* in_sizes, int n_in,
                              void* d_out, int out_size) {
    (void)in_sizes; (void)n_in; (void)out_size;
    const float* X      = (const float*)d_in[0];
    const int*   TE     = (const int*)  d_in[1];
    const float* S0     = (const float*)d_in[2];
    const float* S1     = (const float*)d_in[3];
    const float* W_te1  = (const float*)d_in[4];
    const float* b_te1  = (const float*)d_in[5];
    const float* W_te2  = (const float*)d_in[6];
    const float* b_te2  = (const float*)d_in[7];
    const float* E_se   = (const float*)d_in[8];
    const float* W_in1  = (const float*)d_in[9];
    const float* b_in1  = (const float*)d_in[10];
    const float* W_in2  = (const float*)d_in[11];
    const float* b_in2  = (const float*)d_in[12];
    const float* enc_Wg = (const float*)d_in[13];
    const float* enc_bg = (const float*)d_in[14];
    const float* enc_Wc = (const float*)d_in[15];
    const float* enc_bc = (const float*)d_in[16];
    const float* dec_Wg = (const float*)d_in[17];
    const float* dec_bg = (const float*)d_in[18];
    const float* dec_Wc = (const float*)d_in[19];
    const float* dec_bc = (const float*)d_in[20];
    const float* W_out1 = (const float*)d_in[21];
    const float* b_out1 = (const float*)d_in[22];
    const float* W_out2 = (const float*)d_in[23];
    const float* b_out2 = (const float*)d_in[24];
    float* out = (float*)d_out;

    // prologue
    build_csr_kernel<<<dim3(NN, 2), 32>>>(S0, S1);
    te_kernel<<<BBATCH * TT, DD>>>(TE, W_te1, b_te1, W_te2, b_te2);
    xe_kernel<<<(TT * MROW) / 2, 128>>>(X, W_in1, b_in1, W_in2, b_in2, E_se);
    spmm_kernel<<<dim3(NN, TT, 2), 256>>>(0);                                  // SX
    mma_gemm_kernel<128, 0><<<dim3(MTILES, TT), 256>>>(enc_Wg, dec_Wg, enc_bg, dec_bg, 0); // Gx
    mma_gemm_kernel<64, 1><<<dim3(MTILES, TT), 256>>>(enc_Wc, dec_Wc, enc_bc, dec_bc, 0);  // Cx
    zero_h_kernel<<<(MROW * DD) / 256, 256>>>();

    // recurrence: 12 encoder + 12 decoder steps
    for (int t = 0; t < TT; t++) {
        spmm_kernel<<<dim3(NN, 1, 2), 256>>>(1);                               // [S0h|S1h]
        mma_gemm_kernel<128, 2><<<dim3(MTILES, 1), 256>>>(enc_Wg, dec_Wg, nullptr, nullptr, t); // RU + rh
        spmm_kernel<<<dim3(NN, 1, 2), 256>>>(2);                               // [S0rh|S1rh]
        mma_gemm_kernel<64, 3><<<dim3(MTILES, 1), 256>>>(enc_Wc, dec_Wc, nullptr, nullptr, t);  // c, h-update
        if (t >= PP)
            outhead_kernel<<<MROW / 2, 128>>>(W_out1, b_out1, W_out2, b_out2, out, t - PP);
    }
}